// round 10
// baseline (speedup 1.0000x reference)
#include <cuda_runtime.h>
#include <float.h>

#define BATCH 4
#define NP    8192      // downsampled points per batch (8 frames * 1024)
#define CIN   64
#define COUT  128
#define KNN_K 16
#define NORIG 16384
#define NQ    (BATCH * NP)          // 32768 queries
#define PA    1024                  // phase-A candidates per query (warm-start sample)
#define NSTR  2                     // phase-B streams per query
#define SLEN  3584                  // (NP - PA) / NSTR
#define CHUNK 1792                  // smem tile chunk (28 KB of float4)

// ---------------- scratch (static __device__; no allocs allowed) ----------------
// g_pos4.w stores -|q|^2 so the KNN score d' = 2 p.q - |q|^2 is a pure 3-FMA
// chain. d' differs from -||p-q||^2 by the query-constant |p|^2, which does not
// affect per-query ordering, ties, or selected indices.
__device__ float4 g_pos4[NQ];                    // xyz + (-|p|^2)       (512 KB)
__device__ float  g_tau[NQ];                     // phase-A 16th-best d' (128 KB)
__device__ float  g_pd[(1 + NSTR) * NQ * KNN_K]; // partial top-16 d'    (6 MB)
__device__ int    g_pi[(1 + NSTR) * NQ * KNN_K]; // partial top-16 idxs  (6 MB)
__device__ int    g_knn[NQ * KNN_K];             // final knn indices    (2 MB)
// z[r][c] = (new_x @ Wx + bias)[r][c] + pos[r].wp[c]   (gathered by neighbor j)
// t[r][c] = pos[r].wp[c]                               (subtracted per center n)
// => h[n][k][c] = z[knn[n][k]][c] - t[n][c]  (reassociated vs reference; BN-safe)
__device__ float  g_z[(size_t)NQ * COUT];        // 16 MB
__device__ float  g_t[(size_t)NQ * COUT];        // 16 MB
__device__ float  g_sum[COUT];
__device__ float  g_sumsq[COUT];
__device__ float  g_scale[COUT];                 // rsqrt(var+eps)*gamma
__device__ float  g_shift[COUT];                 // beta - mu*scale
__device__ float  g_mean0[NP * COUT];            // mean over k, batch 0 (4 MB)

// Grouped unsorted top-16: 4 groups of 4 with cached group mins.
// Precondition: d > mn. ~22 instructions on the taken path.
__device__ __forceinline__ void t16_ins(float (&bd)[KNN_K], int (&bi)[KNN_K],
                                        float (&gm)[4], float &mn,
                                        float d, int idx) {
    bool done = false;
#pragma unroll
    for (int g = 0; g < 4; g++) {
        if (!done && gm[g] == mn) {
            done = true;
            bool rep = false;
#pragma unroll
            for (int e = 0; e < 4; e++) {
                if (!rep && bd[g * 4 + e] == mn) {
                    bd[g * 4 + e] = d; bi[g * 4 + e] = idx; rep = true;
                }
            }
            gm[g] = fminf(fminf(bd[g * 4], bd[g * 4 + 1]),
                          fminf(bd[g * 4 + 2], bd[g * 4 + 3]));
        }
    }
    mn = fminf(fminf(gm[0], gm[1]), fminf(gm[2], gm[3]));
}

#define T16_INIT(bd, bi, gm, mn, v)                                       \
    _Pragma("unroll")                                                     \
    for (int _i = 0; _i < KNN_K; _i++) { bd[_i] = (v); bi[_i] = -1; }     \
    gm[0] = gm[1] = gm[2] = gm[3] = (v); mn = (v);

// Vectorized top-16 spill: 16 floats + 16 ints as 4+4 .128 stores.
#define T16_STORE(pd_base, pi_base, bd, bi)                               \
    _Pragma("unroll")                                                     \
    for (int _v = 0; _v < 4; _v++) {                                      \
        reinterpret_cast<float4*>(pd_base)[_v] =                          \
            make_float4(bd[_v*4], bd[_v*4+1], bd[_v*4+2], bd[_v*4+3]);    \
        reinterpret_cast<int4*>(pi_base)[_v] =                            \
            make_int4(bi[_v*4], bi[_v*4+1], bi[_v*4+2], bi[_v*4+3]);      \
    }

// 4-wide gated scan step: one divergent region per 4 candidates; inside, the
// candidates are tested/inserted in index order against the updated mn, so the
// result is bitwise identical to the sequential per-candidate loop.
// Score: d' = 2 p.q - |q|^2, 3 FMA per candidate (tile.w = -|q|^2).
#define SCAN4(tileptr, j, jb)                                              \
    {                                                                      \
        float4 q0 = (tileptr)[(j) + 0];                                    \
        float4 q1 = (tileptr)[(j) + 1];                                    \
        float4 q2 = (tileptr)[(j) + 2];                                    \
        float4 q3 = (tileptr)[(j) + 3];                                    \
        float d0 = fmaf(ax, q0.x, fmaf(ay, q0.y, fmaf(az, q0.z, q0.w)));   \
        float d1 = fmaf(ax, q1.x, fmaf(ay, q1.y, fmaf(az, q1.z, q1.w)));   \
        float d2 = fmaf(ax, q2.x, fmaf(ay, q2.y, fmaf(az, q2.z, q2.w)));   \
        float d3 = fmaf(ax, q3.x, fmaf(ay, q3.y, fmaf(az, q3.z, q3.w)));   \
        float dmx = fmaxf(fmaxf(d0, d1), fmaxf(d2, d3));                   \
        if (dmx > mn) {                                                    \
            if (d0 > mn) t16_ins(bd, bi, gm, mn, d0, (jb) + (j) + 0);      \
            if (d1 > mn) t16_ins(bd, bi, gm, mn, d1, (jb) + (j) + 1);      \
            if (d2 > mn) t16_ins(bd, bi, gm, mn, d2, (jb) + (j) + 2);      \
            if (d3 > mn) t16_ins(bd, bi, gm, mn, d3, (jb) + (j) + 3);      \
        }                                                                  \
    }

// ---------------- K0: downsample pos, pack float4, zero stats, write new_pos ----
__global__ void prep_kernel(const float* __restrict__ pos,
                            float* __restrict__ out, int write_pos) {
    int r = blockIdx.x * blockDim.x + threadIdx.x;
    if (r < COUT) { g_sum[r] = 0.f; g_sumsq[r] = 0.f; }
    if (r >= NQ) return;
    int b = r >> 13;
    int n = r & (NP - 1);
    int f = n >> 10;
    int s = n & 1023;
    int orig = b * NORIG + f * 2048 + s;       // keep every other frame
    float x = pos[orig * 3 + 0];
    float y = pos[orig * 3 + 1];
    float z = pos[orig * 3 + 2];
    g_pos4[r] = make_float4(x, y, z, -(x * x + y * y + z * z));
    if (write_pos) {
        float* op = out + (size_t)NQ * COUT + (size_t)r * 3;
        op[0] = x; op[1] = y; op[2] = z;
    }
}

// ---------------- K1a: phase A — top-16 over candidates [0, PA), publish tau ----
__global__ void __launch_bounds__(256) knn_a_kernel() {
    __shared__ float4 tile[PA];
    int r = blockIdx.x * 256 + threadIdx.x;     // block spans 256 queries, same batch
    int b = r >> 13;
    const float4* base = g_pos4 + b * NP;
    for (int i = threadIdx.x; i < PA; i += 256) tile[i] = base[i];
    __syncthreads();

    float4 p = g_pos4[r];
    float ax = 2.f * p.x, ay = 2.f * p.y, az = 2.f * p.z;

    float bd[KNN_K]; int bi[KNN_K]; float gm[4]; float mn;
    T16_INIT(bd, bi, gm, mn, -FLT_MAX);

#pragma unroll 2
    for (int j = 0; j < PA; j += 4) SCAN4(tile, j, 0)

    T16_STORE(&g_pd[r * KNN_K], &g_pi[r * KNN_K], bd, bi)
    g_tau[r] = mn;
}

// ---------------- K1b: phase B — 2 warm-started streams over [PA, NP) ----------
__global__ void __launch_bounds__(256) knn_b_kernel() {
    __shared__ float4 tile[CHUNK];
    int t = blockIdx.x * 256 + threadIdx.x;     // 0..65535
    int s = t >> 15;                            // stream 0..1 (block-uniform)
    int r = t & (NQ - 1);
    int b = r >> 13;                            // block-uniform (256 | 8192)
    int start = PA + s * SLEN;
    const float4* base = g_pos4 + b * NP + start;

    float4 p = g_pos4[r];
    float ax = 2.f * p.x, ay = 2.f * p.y, az = 2.f * p.z;

    float bd[KNN_K]; int bi[KNN_K]; float gm[4]; float mn;
    // Warm start at tau: candidates with d' <= tau cannot be in the final
    // top-16 (phase A already holds 16 entries >= tau). Sentinels idx=-1.
    T16_INIT(bd, bi, gm, mn, g_tau[r]);

    for (int c0 = 0; c0 < SLEN; c0 += CHUNK) {
        __syncthreads();
        for (int i = threadIdx.x; i < CHUNK; i += 256) tile[i] = base[c0 + i];
        __syncthreads();
        int jbase = start + c0;
#pragma unroll 2
        for (int j = 0; j < CHUNK; j += 4) SCAN4(tile, j, jbase)
    }
    size_t o = (size_t)((1 + s) * NQ + r) * KNN_K;
    T16_STORE(&g_pd[o], &g_pi[o], bd, bi)
}

// ---------------- K1c: merge phase-A list + 2 phase-B lists per query -----------
__global__ void knn_merge_kernel() {
    int r = blockIdx.x * blockDim.x + threadIdx.x;      // 0..NQ-1
    float bd[KNN_K]; int bi[KNN_K]; float gm[4]; float mn;
#pragma unroll
    for (int v = 0; v < 4; v++) {
        float4 dv = reinterpret_cast<const float4*>(&g_pd[r * KNN_K])[v];
        int4   iv = reinterpret_cast<const int4*>(&g_pi[r * KNN_K])[v];
        bd[v*4+0] = dv.x; bd[v*4+1] = dv.y; bd[v*4+2] = dv.z; bd[v*4+3] = dv.w;
        bi[v*4+0] = iv.x; bi[v*4+1] = iv.y; bi[v*4+2] = iv.z; bi[v*4+3] = iv.w;
    }
#pragma unroll
    for (int g = 0; g < 4; g++)
        gm[g] = fminf(fminf(bd[g * 4], bd[g * 4 + 1]),
                      fminf(bd[g * 4 + 2], bd[g * 4 + 3]));
    mn = fminf(fminf(gm[0], gm[1]), fminf(gm[2], gm[3]));
#pragma unroll
    for (int L = 1; L <= NSTR; L++) {
        size_t o = (size_t)(L * NQ + r) * KNN_K;
#pragma unroll
        for (int v = 0; v < 4; v++) {
            float4 dv = reinterpret_cast<const float4*>(&g_pd[o])[v];
            int4   iv = reinterpret_cast<const int4*>(&g_pi[o])[v];
#pragma unroll
            for (int e = 0; e < 4; e++) {
                float d = (e == 0) ? dv.x : (e == 1) ? dv.y : (e == 2) ? dv.z : dv.w;
                int idx = (e == 0) ? iv.x : (e == 1) ? iv.y : (e == 2) ? iv.z : iv.w;
                if (d > mn) t16_ins(bd, bi, gm, mn, d, idx);  // sentinels excluded
            }
        }
    }
#pragma unroll
    for (int v = 0; v < 4; v++)
        reinterpret_cast<int4*>(&g_knn[r * KNN_K])[v] =
            make_int4(bi[v*4], bi[v*4+1], bi[v*4+2], bi[v*4+3]);
}

// ---------------- K2: z = new_x @ Wx + bias + pos.wp,  t = pos.wp ---------------
__global__ void __launch_bounds__(128) yz_kernel(const float* __restrict__ x,
                                                 const float* __restrict__ W,
                                                 const float* __restrict__ bias) {
    __shared__ float xs[4][CIN];
    int tid = threadIdx.x;                      // channel
    float Wr[CIN];
#pragma unroll
    for (int k = 0; k < CIN; ++k) Wr[k] = W[k * COUT + tid];
    float bc  = bias[tid];
    float wp0 = W[64 * COUT + tid];
    float wp1 = W[65 * COUT + tid];
    float wp2 = W[66 * COUT + tid];
    int row0 = blockIdx.x * 64;                 // 512 blocks * 64 rows
    for (int rr = 0; rr < 64; rr += 4) {
        __syncthreads();
#pragma unroll
        for (int q = 0; q < 4; ++q) {
            int r = row0 + rr + q;
            int b = r >> 13;
            int n = r & (NP - 1);
            int f = n >> 10;
            int s = n & 1023;
            const float* xp = x + (size_t)(b * NORIG + f * 2048 + s) * CIN;
            if (tid < CIN) xs[q][tid] = xp[tid];
        }
        __syncthreads();
        float a0 = bc, a1 = bc, a2 = bc, a3 = bc;
#pragma unroll
        for (int k = 0; k < CIN; ++k) {
            float w = Wr[k];
            a0 = fmaf(xs[0][k], w, a0);
            a1 = fmaf(xs[1][k], w, a1);
            a2 = fmaf(xs[2][k], w, a2);
            a3 = fmaf(xs[3][k], w, a3);
        }
        size_t o = (size_t)(row0 + rr) * COUT + tid;
#pragma unroll
        for (int q = 0; q < 4; ++q) {
            float4 p = g_pos4[row0 + rr + q];   // converged load
            float tq = fmaf(p.x, wp0, fmaf(p.y, wp1, p.z * wp2));
            float aq = (q == 0) ? a0 : (q == 1) ? a1 : (q == 2) ? a2 : a3;
            g_t[o + q * COUT] = tq;
            g_z[o + q * COUT] = aq + tq;
        }
    }
}

// ---------------- K3: BN statistics (sum, sumsq per channel) --------------------
// h = z[j][c] - t[r][c]; 1 gather LDG + 3 FLOP per element.
__global__ void stats_kernel() {
    int c = threadIdx.x;   // 128 channels
    float s = 0.f, q = 0.f;
    int r0 = blockIdx.x * 32;                   // 1024 blocks * 32 rows
    for (int i = 0; i < 32; ++i) {
        int r = r0 + i;
        size_t broot = (size_t)((r >> 13) << 13);
        float tn = g_t[(size_t)r * COUT + c];
        const int4* kp = reinterpret_cast<const int4*>(&g_knn[r * KNN_K]);
#pragma unroll
        for (int v = 0; v < 4; ++v) {
            int4 jj = kp[v];
#pragma unroll
            for (int e = 0; e < 4; ++e) {
                int j = (e == 0) ? jj.x : (e == 1) ? jj.y : (e == 2) ? jj.z : jj.w;
                float h = g_z[(broot + j) * COUT + c] - tn;
                s += h;
                q = fmaf(h, h, q);
            }
        }
    }
    atomicAdd(&g_sum[c], s);
    atomicAdd(&g_sumsq[c], q);
}

// ---------------- K4: fold BN affine --------------------------------------------
__global__ void finalize_kernel(const float* __restrict__ gamma,
                                const float* __restrict__ beta) {
    int c = threadIdx.x;
    const float M = (float)((size_t)NQ * KNN_K);
    float mu  = g_sum[c] / M;
    float var = g_sumsq[c] / M - mu * mu;       // biased var, same as reference
    float rs  = rsqrtf(var + 1e-5f);
    float a   = rs * gamma[c];
    g_scale[c] = a;
    g_shift[c] = beta[c] - mu * a;
}

// ---------------- K5a: batch 0 — out = max_k + mean_k, publish mean0 ------------
__global__ void out0_kernel(float* __restrict__ out) {
    int c = threadIdx.x;
    float a  = g_scale[c];
    float sh = g_shift[c];
    int r0 = blockIdx.x * 8;                    // 1024 blocks * 8 rows (batch 0)
    for (int i = 0; i < 8; ++i) {
        int r = r0 + i;
        float tn = g_t[(size_t)r * COUT + c];
        float sh2 = sh - tn * a;                // fold -tn into the BN shift
        float mx = 0.f;                         // relu outputs are >= 0
        float sm = 0.f;
        const int4* kp = reinterpret_cast<const int4*>(&g_knn[r * KNN_K]);
#pragma unroll
        for (int v = 0; v < 4; ++v) {
            int4 jj = kp[v];
#pragma unroll
            for (int e = 0; e < 4; ++e) {
                int j = (e == 0) ? jj.x : (e == 1) ? jj.y : (e == 2) ? jj.z : jj.w;
                float rl = fmaxf(fmaf(g_z[(size_t)j * COUT + c], a, sh2), 0.f);
                mx = fmaxf(mx, rl);
                sm += rl;
            }
        }
        float mean = sm * 0.0625f;              // /16 exact
        g_mean0[r * COUT + c] = mean;
        out[(size_t)r * COUT + c] = mx + mean;
    }
}

// ---------------- K5b: batches 1-3 — out = max_k + mean0 (fused broadcast) ------
__global__ void out123_kernel(float* __restrict__ out) {
    int c = threadIdx.x;
    float a  = g_scale[c];
    float sh = g_shift[c];
    int r0 = NP + blockIdx.x * 8;               // 3072 blocks * 8 rows
    for (int i = 0; i < 8; ++i) {
        int r = r0 + i;
        size_t broot = (size_t)((r >> 13) << 13);
        float tn = g_t[(size_t)r * COUT + c];
        float sh2 = sh - tn * a;
        float mx = 0.f;
        const int4* kp = reinterpret_cast<const int4*>(&g_knn[r * KNN_K]);
#pragma unroll
        for (int v = 0; v < 4; ++v) {
            int4 jj = kp[v];
#pragma unroll
            for (int e = 0; e < 4; ++e) {
                int j = (e == 0) ? jj.x : (e == 1) ? jj.y : (e == 2) ? jj.z : jj.w;
                float rl = fmaxf(fmaf(g_z[(broot + j) * COUT + c], a, sh2), 0.f);
                mx = fmaxf(mx, rl);
            }
        }
        out[(size_t)r * COUT + c] = mx + g_mean0[(r & (NP - 1)) * COUT + c];
    }
}

// ---------------- launch --------------------------------------------------------
extern "C" void kernel_launch(void* const* d_in, const int* in_sizes, int n_in,
                              void* d_out, int out_size) {
    const float* x     = (const float*)d_in[0];
    const float* pos   = (const float*)d_in[1];
    const float* W     = (const float*)d_in[2];
    const float* bias  = (const float*)d_in[3];
    const float* gamma = (const float*)d_in[4];
    const float* beta  = (const float*)d_in[5];
    float* out = (float*)d_out;

    int write_pos = (out_size >= NQ * COUT + NQ * 3) ? 1 : 0;

    prep_kernel     <<<128,  256>>>(pos, out, write_pos);
    knn_a_kernel    <<<128,  256>>>();
    knn_b_kernel    <<<256,  256>>>();
    knn_merge_kernel<<<128,  256>>>();
    yz_kernel       <<<512,  128>>>(x, W, bias);
    stats_kernel    <<<1024, 128>>>();
    finalize_kernel <<<1,    128>>>(gamma, beta);
    out0_kernel     <<<1024, 128>>>(out);
    out123_kernel   <<<3072, 128>>>(out);
}